// round 2
// baseline (speedup 1.0000x reference)
#include <cuda_runtime.h>
#include <cuda_bf16.h>
#include <cstddef>

// Problem constants (fixed shapes)
#define BATCH 8
#define SEQ   1024
#define CDIM  768
#define HEADS 12
#define HDIM  64
#define MTOK  (BATCH*SEQ)      // 8192
#define QKVC  (3*CDIM)         // 2304
#define SCALE 0.125f           // 64^-0.5

// Scratch (device globals — no allocation allowed)
__device__ float g_qkv[(size_t)MTOK * QKVC];   // [8192, 2304] row-major
__device__ float g_ctx[(size_t)MTOK * CDIM];   // [8192, 768]  (B,N,C with c=h*64+d)

// ---------------------------------------------------------------------------
// Generic GEMM: Y[M,Nc] = X[M,K] @ W[Nc,K]^T (+ bias). 128x128 tile, BK=16,
// 256 threads, 8x8 per thread.
// ---------------------------------------------------------------------------
__global__ __launch_bounds__(256) void gemm_xwT(
    const float* __restrict__ X, const float* __restrict__ W,
    const float* __restrict__ bias, float* __restrict__ Y,
    int M, int Nc, int K)
{
    __shared__ float As[16][128];
    __shared__ float Bs[16][128];

    const int tid = threadIdx.x;
    const int tx = tid % 16;
    const int ty = tid / 16;
    const int rowBase = blockIdx.y * 128;
    const int colBase = blockIdx.x * 128;

    const int lr = tid / 4;         // 0..63
    const int lk = (tid % 4) * 4;   // 0,4,8,12

    float acc[8][8];
#pragma unroll
    for (int i = 0; i < 8; i++)
#pragma unroll
        for (int j = 0; j < 8; j++) acc[i][j] = 0.0f;

    for (int kt = 0; kt < K; kt += 16) {
#pragma unroll
        for (int p = 0; p < 2; p++) {
            int r = lr + p * 64;
            float4 av = *(const float4*)&X[(size_t)(rowBase + r) * K + kt + lk];
            As[lk + 0][r] = av.x; As[lk + 1][r] = av.y;
            As[lk + 2][r] = av.z; As[lk + 3][r] = av.w;
            float4 bv = *(const float4*)&W[(size_t)(colBase + r) * K + kt + lk];
            Bs[lk + 0][r] = bv.x; Bs[lk + 1][r] = bv.y;
            Bs[lk + 2][r] = bv.z; Bs[lk + 3][r] = bv.w;
        }
        __syncthreads();

#pragma unroll
        for (int k = 0; k < 16; k++) {
            float a[8], b[8];
            *(float4*)&a[0] = *(const float4*)&As[k][ty * 8];
            *(float4*)&a[4] = *(const float4*)&As[k][ty * 8 + 4];
            *(float4*)&b[0] = *(const float4*)&Bs[k][tx * 8];
            *(float4*)&b[4] = *(const float4*)&Bs[k][tx * 8 + 4];
#pragma unroll
            for (int i = 0; i < 8; i++)
#pragma unroll
                for (int j = 0; j < 8; j++)
                    acc[i][j] = fmaf(a[i], b[j], acc[i][j]);
        }
        __syncthreads();
    }

#pragma unroll
    for (int i = 0; i < 8; i++) {
        int r = rowBase + ty * 8 + i;
#pragma unroll
        for (int j = 0; j < 8; j++) {
            int c = colBase + tx * 8 + j;
            float v = acc[i][j];
            if (bias) v += bias[c];
            Y[(size_t)r * Nc + c] = v;
        }
    }
}

// ---------------------------------------------------------------------------
// Fused attention: per block (32 query rows, one (b,h)).
// S[32][1024] lives in smem. Writes attn once; accumulates AV; writes ctx.
// ---------------------------------------------------------------------------
#define SROW 1028   // padded stride for S (mult of 4 -> float4 stores OK)

__global__ __launch_bounds__(256) void attn_fused(
    float* __restrict__ attn_out,   // [B,H,N,N]
    float* __restrict__ ctx_out)    // [B,N,C]
{
    extern __shared__ float sm[];
    float* S  = sm;                      // 32*1028 = 32896 floats
    float* Qs = S + 32 * SROW;           // [64][36] (d-major)
    float* KV = Qs + 64 * 36;            // K: [64][132] (8448) / V: [128][68] (8704)

    const int nb = blockIdx.x;   // query tile (32 rows)
    const int h  = blockIdx.y;
    const int b  = blockIdx.z;
    const int tid = threadIdx.x;
    const int tx = tid % 32;
    const int ty = tid / 32;     // 0..7 == warp id

    const float* qkv = g_qkv;
    const size_t tokbase = (size_t)b * SEQ * QKVC;
    const int qoff = h * HDIM;
    const int koff = CDIM + h * HDIM;
    const int voff = 2 * CDIM + h * HDIM;

    // ---- load Q tile (32 x 64), store transposed Qs[d][r] ----
    {
        int r  = tid / 8;
        int d4 = (tid % 8) * 8;
        const float* src = qkv + tokbase + (size_t)(nb * 32 + r) * QKVC + qoff + d4;
        float4 a0 = *(const float4*)src;
        float4 a1 = *(const float4*)(src + 4);
        Qs[(d4 + 0) * 36 + r] = a0.x; Qs[(d4 + 1) * 36 + r] = a0.y;
        Qs[(d4 + 2) * 36 + r] = a0.z; Qs[(d4 + 3) * 36 + r] = a0.w;
        Qs[(d4 + 4) * 36 + r] = a1.x; Qs[(d4 + 5) * 36 + r] = a1.y;
        Qs[(d4 + 6) * 36 + r] = a1.z; Qs[(d4 + 7) * 36 + r] = a1.w;
    }
    __syncthreads();

    // ---- S = scale * Q @ K^T, tiled over 128 keys at a time ----
    for (int mb = 0; mb < 8; mb++) {
        // load K tile (128 keys x 64 dims), transposed KV[d][m] stride 132
#pragma unroll
        for (int p = 0; p < 8; p++) {
            int mm = p * 16 + tid / 16;
            int d4 = (tid % 16) * 4;
            float4 kv4 = *(const float4*)(qkv + tokbase +
                          (size_t)(mb * 128 + mm) * QKVC + koff + d4);
            KV[(d4 + 0) * 132 + mm] = kv4.x;
            KV[(d4 + 1) * 132 + mm] = kv4.y;
            KV[(d4 + 2) * 132 + mm] = kv4.z;
            KV[(d4 + 3) * 132 + mm] = kv4.w;
        }
        __syncthreads();

        float c[4][4];
#pragma unroll
        for (int i = 0; i < 4; i++)
#pragma unroll
            for (int j = 0; j < 4; j++) c[i][j] = 0.0f;

#pragma unroll 8
        for (int d = 0; d < 64; d++) {
            float4 qv  = *(const float4*)&Qs[d * 36 + ty * 4];
            float4 kv4 = *(const float4*)&KV[d * 132 + tx * 4];
            c[0][0] = fmaf(qv.x, kv4.x, c[0][0]); c[0][1] = fmaf(qv.x, kv4.y, c[0][1]);
            c[0][2] = fmaf(qv.x, kv4.z, c[0][2]); c[0][3] = fmaf(qv.x, kv4.w, c[0][3]);
            c[1][0] = fmaf(qv.y, kv4.x, c[1][0]); c[1][1] = fmaf(qv.y, kv4.y, c[1][1]);
            c[1][2] = fmaf(qv.y, kv4.z, c[1][2]); c[1][3] = fmaf(qv.y, kv4.w, c[1][3]);
            c[2][0] = fmaf(qv.z, kv4.x, c[2][0]); c[2][1] = fmaf(qv.z, kv4.y, c[2][1]);
            c[2][2] = fmaf(qv.z, kv4.z, c[2][2]); c[2][3] = fmaf(qv.z, kv4.w, c[2][3]);
            c[3][0] = fmaf(qv.w, kv4.x, c[3][0]); c[3][1] = fmaf(qv.w, kv4.y, c[3][1]);
            c[3][2] = fmaf(qv.w, kv4.z, c[3][2]); c[3][3] = fmaf(qv.w, kv4.w, c[3][3]);
        }
#pragma unroll
        for (int i = 0; i < 4; i++) {
            float4 o = make_float4(c[i][0] * SCALE, c[i][1] * SCALE,
                                   c[i][2] * SCALE, c[i][3] * SCALE);
            *(float4*)&S[(ty * 4 + i) * SROW + mb * 128 + tx * 4] = o;
        }
        __syncthreads();
    }

    // ---- softmax (each warp owns 4 rows), write attn ----
    {
        const int lane = tx;
#pragma unroll
        for (int q = 0; q < 4; q++) {
            int r = ty * 4 + q;
            float* Sr = &S[r * SROW];
            float mx = -1e30f;
            for (int m = lane; m < 1024; m += 32) mx = fmaxf(mx, Sr[m]);
#pragma unroll
            for (int o = 16; o > 0; o >>= 1)
                mx = fmaxf(mx, __shfl_xor_sync(0xffffffffu, mx, o));
            float sum = 0.0f;
            for (int m = lane; m < 1024; m += 32) {
                float e = __expf(Sr[m] - mx);
                Sr[m] = e;
                sum += e;
            }
#pragma unroll
            for (int o = 16; o > 0; o >>= 1)
                sum += __shfl_xor_sync(0xffffffffu, sum, o);
            float inv = 1.0f / sum;
            float* dst = attn_out +
                ((size_t)(b * HEADS + h) * SEQ + nb * 32 + r) * SEQ;
            for (int m = lane; m < 1024; m += 32) {
                float p = Sr[m] * inv;
                Sr[m] = p;
                dst[m] = p;
            }
        }
    }
    __syncthreads();

    // ---- O = P @ V (32 x 64), V tiled 128 rows at a time ----
    float o2[4][2];
#pragma unroll
    for (int i = 0; i < 4; i++) { o2[i][0] = 0.0f; o2[i][1] = 0.0f; }

    for (int mb = 0; mb < 8; mb++) {
#pragma unroll
        for (int p = 0; p < 8; p++) {
            int mm = p * 16 + tid / 16;
            int d4 = (tid % 16) * 4;
            float4 vv = *(const float4*)(qkv + tokbase +
                         (size_t)(mb * 128 + mm) * QKVC + voff + d4);
            *(float4*)&KV[mm * 68 + d4] = vv;
        }
        __syncthreads();

#pragma unroll 4
        for (int mm = 0; mm < 128; mm++) {
            float2 vv = *(const float2*)&KV[mm * 68 + tx * 2];
#pragma unroll
            for (int i = 0; i < 4; i++) {
                float p = S[(ty * 4 + i) * SROW + mb * 128 + mm];
                o2[i][0] = fmaf(p, vv.x, o2[i][0]);
                o2[i][1] = fmaf(p, vv.y, o2[i][1]);
            }
        }
        __syncthreads();
    }

#pragma unroll
    for (int i = 0; i < 4; i++) {
        int n = nb * 32 + ty * 4 + i;
        float* dst = ctx_out + ((size_t)b * SEQ + n) * CDIM + h * HDIM + tx * 2;
        dst[0] = o2[i][0];
        dst[1] = o2[i][1];
    }
}

// ---------------------------------------------------------------------------
extern "C" void kernel_launch(void* const* d_in, const int* in_sizes, int n_in,
                              void* d_out, int out_size)
{
    const float* x      = (const float*)d_in[0];   // [8,1024,768]
    const float* qkv_w  = (const float*)d_in[1];   // [2304,768]
    const float* proj_w = (const float*)d_in[2];   // [768,768]
    const float* proj_b = (const float*)d_in[3];   // [768]

    float* out_proj = (float*)d_out;                              // [8,1024,768]
    float* out_attn = (float*)d_out + (size_t)MTOK * CDIM;        // [8,12,1024,1024]

    float* qkv_scratch = nullptr;
    float* ctx_scratch = nullptr;
    cudaGetSymbolAddress((void**)&qkv_scratch, g_qkv);
    cudaGetSymbolAddress((void**)&ctx_scratch, g_ctx);

    const int attn_smem = (32 * SROW + 64 * 36 + 128 * 68) * (int)sizeof(float);
    cudaFuncSetAttribute(attn_fused,
                         cudaFuncAttributeMaxDynamicSharedMemorySize, attn_smem);

    // 1) QKV GEMM: [8192,768] @ [2304,768]^T -> [8192,2304]
    gemm_xwT<<<dim3(QKVC / 128, MTOK / 128), 256>>>(
        x, qkv_w, nullptr, qkv_scratch, MTOK, QKVC, CDIM);

    // 2) Fused attention (scores + softmax + attn write + AV)
    attn_fused<<<dim3(SEQ / 32, HEADS, BATCH), 256, attn_smem>>>(
        out_attn, ctx_scratch);

    // 3) Projection GEMM + bias: [8192,768] @ [768,768]^T + b -> out
    gemm_xwT<<<dim3(CDIM / 128, MTOK / 128), 256>>>(
        ctx_scratch, proj_w, proj_b, out_proj, MTOK, CDIM, CDIM);
}

// round 4
// speedup vs baseline: 1.9879x; 1.9879x over previous
#include <cuda_runtime.h>
#include <cuda_bf16.h>
#include <cstdint>
#include <cstddef>

#define BATCH 8
#define SEQ   1024
#define CDIM  768
#define HEADS 12
#define MTOK  (BATCH*SEQ)      // 8192
#define QKVC  (3*CDIM)         // 2304

// Scratch (device globals — allocation is forbidden)
__device__ float g_qkv[(size_t)MTOK * QKVC];   // [8192, 2304]
__device__ float g_ctx[(size_t)MTOK * CDIM];   // [8192, 768]

// ---------------------------------------------------------------------------
// mma.sync m16n8k16 bf16 with fp32 accumulate
// ---------------------------------------------------------------------------
__device__ __forceinline__ void mma16816(float* d, const uint32_t* a, const uint32_t* b)
{
    asm volatile(
        "mma.sync.aligned.m16n8k16.row.col.f32.bf16.bf16.f32 "
        "{%0,%1,%2,%3},{%4,%5,%6,%7},{%8,%9},{%0,%1,%2,%3};\n"
        : "+f"(d[0]), "+f"(d[1]), "+f"(d[2]), "+f"(d[3])
        : "r"(a[0]), "r"(a[1]), "r"(a[2]), "r"(a[3]), "r"(b[0]), "r"(b[1]));
}

// split fp32 pair -> (hi, mid) bf16x2 pairs
__device__ __forceinline__ void cvt_pair(float x, float y, uint32_t& hi, uint32_t& mid)
{
    __nv_bfloat162 h = __floats2bfloat162_rn(x, y);
    float rx = x - __bfloat162float(__low2bfloat16(h));
    float ry = y - __bfloat162float(__high2bfloat16(h));
    __nv_bfloat162 m = __floats2bfloat162_rn(rx, ry);
    hi  = *reinterpret_cast<uint32_t*>(&h);
    mid = *reinterpret_cast<uint32_t*>(&m);
}

// ---------------------------------------------------------------------------
// Batched GEMM: C = alpha * A @ B^T (+bias), bf16x3 (hi/mid split, 3 MMAs).
//   A: [M,K] row-major, lda. B layout BL=0: [N,K] row-major ldb (K-contig);
//   BL=1: [K,N] row-major ldb (N-contig). Batch offset: z -> z1=z/nz2, z2=z%nz2,
//   off = z1*s1 + z2*s2 (elements).
//   Block tile BM x BN, BK=32, 256 threads, double-buffered smem, reg staging.
// ---------------------------------------------------------------------------
template<int BM, int BN, int WM, int WN, int BL>
__global__ __launch_bounds__(256, 1) void gemm3(
    const float* __restrict__ Abase, int lda, long long sa1, long long sa2,
    const float* __restrict__ Bbase, int ldb, long long sb1, long long sb2,
    float* __restrict__ Cbase, int ldc, long long sc1, long long sc2,
    int K, int nz2, float alpha, const float* __restrict__ bias)
{
    constexpr int BK  = 32;
    constexpr int BKP = 36;                 // padded k-stride
    constexpr int MW  = BM / WM;            // warps along M
    constexpr int MF  = WM / 16;            // 16-row m-frags per warp
    constexpr int NF  = WN / 8;             // 8-col n-frags per warp
    constexpr int BITER = (BN * BK) / (256 * 4);

    extern __shared__ __nv_bfloat16 sm[];
    __nv_bfloat16* Asm = sm;                       // [2][2][BM][BKP]
    __nv_bfloat16* Bsm = sm + 4 * BM * BKP;        // [2][2][BN][BKP]
#define ASM(bb,s,m,k) Asm[(((bb)*2+(s))*BM + (m))*BKP + (k)]
#define BSM(bb,s,n,k) Bsm[(((bb)*2+(s))*BN + (n))*BKP + (k)]

    const int z  = blockIdx.z;
    const int z1 = z / nz2, z2 = z - z1 * nz2;
    const float* A = Abase + (size_t)z1 * sa1 + (size_t)z2 * sa2;
    const float* B = Bbase + (size_t)z1 * sb1 + (size_t)z2 * sb2;
    float*       C = Cbase + (size_t)z1 * sc1 + (size_t)z2 * sc2;

    const int m0  = blockIdx.y * BM;
    const int n0  = blockIdx.x * BN;
    const int tid = threadIdx.x;
    const int w    = tid >> 5, lane = tid & 31;
    const int wm   = w % MW,   wn   = w / MW;
    const int g    = lane >> 2;
    const int t2   = (lane & 3) * 2;

    float acc[MF][NF][4];
#pragma unroll
    for (int i = 0; i < MF; i++)
#pragma unroll
        for (int j = 0; j < NF; j++)
#pragma unroll
            for (int q = 0; q < 4; q++) acc[i][j][q] = 0.0f;

    // staging registers
    float4 ra[4];
    float4 rb[BITER];

    const int sm_row = tid >> 1;            // A staging row (BM=128)
    const int sm_kq  = (tid & 1) * 16;      // A staging k-offset

    // NOTE: internal loop vars are ldi/sti — must NOT shadow any name used in
    // macro arguments (R3 bug: inner `it` shadowed the caller's `it` inside
    // the expansion of `ktb`, so B tiles never advanced through K).
#define LOAD_TILE(ktb)                                                          \
    {                                                                           \
        const float* Ap = A + (size_t)(m0 + sm_row) * lda + (ktb) + sm_kq;      \
        _Pragma("unroll")                                                       \
        for (int ldj = 0; ldj < 4; ldj++)                                       \
            ra[ldj] = *(const float4*)(Ap + 4 * ldj);                           \
        _Pragma("unroll")                                                       \
        for (int ldi = 0; ldi < BITER; ldi++) {                                 \
            int idx = (tid + ldi * 256) * 4;                                    \
            if (BL == 0) {                                                      \
                int n = idx / BK, kk = idx % BK;                                \
                rb[ldi] = *(const float4*)(B + (size_t)(n0 + n) * ldb + (ktb) + kk); \
            } else {                                                            \
                int kk = idx / BN, n = idx % BN;                                \
                rb[ldi] = *(const float4*)(B + (size_t)((ktb) + kk) * ldb + n0 + n); \
            }                                                                   \
        }                                                                       \
    }

#define STORE_TILE(bb)                                                          \
    {                                                                           \
        _Pragma("unroll")                                                       \
        for (int stj = 0; stj < 4; stj++) {                                     \
            uint32_t hi, mid;                                                   \
            cvt_pair(ra[stj].x, ra[stj].y, hi, mid);                            \
            *(uint32_t*)&ASM(bb, 0, sm_row, sm_kq + 4 * stj)     = hi;          \
            *(uint32_t*)&ASM(bb, 1, sm_row, sm_kq + 4 * stj)     = mid;         \
            cvt_pair(ra[stj].z, ra[stj].w, hi, mid);                            \
            *(uint32_t*)&ASM(bb, 0, sm_row, sm_kq + 4 * stj + 2) = hi;          \
            *(uint32_t*)&ASM(bb, 1, sm_row, sm_kq + 4 * stj + 2) = mid;         \
        }                                                                       \
        _Pragma("unroll")                                                       \
        for (int sti = 0; sti < BITER; sti++) {                                 \
            int idx = (tid + sti * 256) * 4;                                    \
            if (BL == 0) {                                                      \
                int n = idx / BK, kk = idx % BK;                                \
                uint32_t hi, mid;                                               \
                cvt_pair(rb[sti].x, rb[sti].y, hi, mid);                        \
                *(uint32_t*)&BSM(bb, 0, n, kk)     = hi;                        \
                *(uint32_t*)&BSM(bb, 1, n, kk)     = mid;                       \
                cvt_pair(rb[sti].z, rb[sti].w, hi, mid);                        \
                *(uint32_t*)&BSM(bb, 0, n, kk + 2) = hi;                        \
                *(uint32_t*)&BSM(bb, 1, n, kk + 2) = mid;                       \
            } else {                                                            \
                int kk = idx / BN, n = idx % BN;                                \
                float e[4] = { rb[sti].x, rb[sti].y, rb[sti].z, rb[sti].w };    \
                _Pragma("unroll")                                               \
                for (int q = 0; q < 4; q++) {                                   \
                    __nv_bfloat16 h = __float2bfloat16_rn(e[q]);                \
                    BSM(bb, 0, n + q, kk) = h;                                  \
                    BSM(bb, 1, n + q, kk) =                                     \
                        __float2bfloat16_rn(e[q] - __bfloat162float(h));        \
                }                                                               \
            }                                                                   \
        }                                                                       \
    }

    const int iters = K / BK;

    LOAD_TILE(0);
    STORE_TILE(0);
    __syncthreads();

    for (int it = 0; it < iters; it++) {
        const int buf = it & 1;
        const bool more = (it + 1 < iters);
        if (more) LOAD_TILE((it + 1) * BK);

        // compute on buf
#pragma unroll
        for (int ks = 0; ks < BK; ks += 16) {
            uint32_t af[2][MF][4], bf[2][NF][2];
#pragma unroll
            for (int s = 0; s < 2; s++) {
#pragma unroll
                for (int i = 0; i < MF; i++) {
                    int m = wm * WM + i * 16 + g;
                    af[s][i][0] = *(const uint32_t*)&ASM(buf, s, m,     ks + t2);
                    af[s][i][1] = *(const uint32_t*)&ASM(buf, s, m + 8, ks + t2);
                    af[s][i][2] = *(const uint32_t*)&ASM(buf, s, m,     ks + t2 + 8);
                    af[s][i][3] = *(const uint32_t*)&ASM(buf, s, m + 8, ks + t2 + 8);
                }
#pragma unroll
                for (int j = 0; j < NF; j++) {
                    int n = wn * WN + j * 8 + g;
                    bf[s][j][0] = *(const uint32_t*)&BSM(buf, s, n, ks + t2);
                    bf[s][j][1] = *(const uint32_t*)&BSM(buf, s, n, ks + t2 + 8);
                }
            }
#pragma unroll
            for (int i = 0; i < MF; i++)
#pragma unroll
                for (int j = 0; j < NF; j++) {
                    mma16816(acc[i][j], af[0][i], bf[0][j]);   // hi*hi
                    mma16816(acc[i][j], af[0][i], bf[1][j]);   // hi*mid
                    mma16816(acc[i][j], af[1][i], bf[0][j]);   // mid*hi
                }
        }

        if (more) STORE_TILE(buf ^ 1);
        __syncthreads();
    }

    // ---- epilogue ----
#pragma unroll
    for (int i = 0; i < MF; i++) {
        int r = m0 + wm * WM + i * 16 + g;
#pragma unroll
        for (int j = 0; j < NF; j++) {
            int c = n0 + wn * WN + j * 8 + t2;
            float b0 = bias ? bias[c]     : 0.0f;
            float b1 = bias ? bias[c + 1] : 0.0f;
            float2 v0 = make_float2(alpha * acc[i][j][0] + b0, alpha * acc[i][j][1] + b1);
            float2 v1 = make_float2(alpha * acc[i][j][2] + b0, alpha * acc[i][j][3] + b1);
            *(float2*)&C[(size_t)r * ldc + c]       = v0;
            *(float2*)&C[(size_t)(r + 8) * ldc + c] = v1;
        }
    }
#undef ASM
#undef BSM
#undef LOAD_TILE
#undef STORE_TILE
}

// ---------------------------------------------------------------------------
// In-place row softmax over attn [rows, 1024]. One warp per row.
// ---------------------------------------------------------------------------
__global__ __launch_bounds__(256) void softmax_rows(float* __restrict__ attn)
{
    const int lane = threadIdx.x & 31;
    const size_t row = (size_t)blockIdx.x * 8 + (threadIdx.x >> 5);
    float* p = attn + row * SEQ;

    float4 v[8];
    float mx = -3.4e38f;
#pragma unroll
    for (int i = 0; i < 8; i++) {
        v[i] = *(const float4*)&p[(i * 32 + lane) * 4];
        mx = fmaxf(mx, fmaxf(fmaxf(v[i].x, v[i].y), fmaxf(v[i].z, v[i].w)));
    }
#pragma unroll
    for (int o = 16; o > 0; o >>= 1)
        mx = fmaxf(mx, __shfl_xor_sync(0xffffffffu, mx, o));

    float s = 0.0f;
#pragma unroll
    for (int i = 0; i < 8; i++) {
        v[i].x = __expf(v[i].x - mx);
        v[i].y = __expf(v[i].y - mx);
        v[i].z = __expf(v[i].z - mx);
        v[i].w = __expf(v[i].w - mx);
        s += (v[i].x + v[i].y) + (v[i].z + v[i].w);
    }
#pragma unroll
    for (int o = 16; o > 0; o >>= 1)
        s += __shfl_xor_sync(0xffffffffu, s, o);
    const float inv = 1.0f / s;

#pragma unroll
    for (int i = 0; i < 8; i++) {
        v[i].x *= inv; v[i].y *= inv; v[i].z *= inv; v[i].w *= inv;
        *(float4*)&p[(i * 32 + lane) * 4] = v[i];
    }
}

// ---------------------------------------------------------------------------
extern "C" void kernel_launch(void* const* d_in, const int* in_sizes, int n_in,
                              void* d_out, int out_size)
{
    const float* x      = (const float*)d_in[0];   // [8,1024,768]
    const float* qkv_w  = (const float*)d_in[1];   // [2304,768]
    const float* proj_w = (const float*)d_in[2];   // [768,768]
    const float* proj_b = (const float*)d_in[3];   // [768]

    float* out_proj = (float*)d_out;                          // [8,1024,768]
    float* out_attn = (float*)d_out + (size_t)MTOK * CDIM;    // [8,12,1024,1024]

    float* qkv_s = nullptr;
    float* ctx_s = nullptr;
    cudaGetSymbolAddress((void**)&qkv_s, g_qkv);
    cudaGetSymbolAddress((void**)&ctx_s, g_ctx);

    constexpr int SM_BIG = 2 * 2 * (128 + 128) * 36 * 2;  // 73728 B
    constexpr int SM_PV  = 2 * 2 * (128 + 64)  * 36 * 2;  // 55296 B

    cudaFuncSetAttribute((const void*)gemm3<128,128,64,32,0>,
                         cudaFuncAttributeMaxDynamicSharedMemorySize, SM_BIG);
    cudaFuncSetAttribute((const void*)gemm3<128,64,32,32,1>,
                         cudaFuncAttributeMaxDynamicSharedMemorySize, SM_PV);

    // 1) QKV GEMM: [8192,768] @ [2304,768]^T -> g_qkv
    gemm3<128,128,64,32,0><<<dim3(QKVC/128, MTOK/128, 1), 256, SM_BIG>>>(
        x, CDIM, 0, 0,
        qkv_w, CDIM, 0, 0,
        qkv_s, QKVC, 0, 0,
        CDIM, 1, 1.0f, nullptr);

    // 2) S = 0.125 * Q @ K^T (batched over b*12+h) -> out_attn (raw scores)
    gemm3<128,128,64,32,0><<<dim3(SEQ/128, SEQ/128, BATCH*HEADS), 256, SM_BIG>>>(
        qkv_s,        QKVC, (long long)SEQ * QKVC, 64,
        qkv_s + CDIM, QKVC, (long long)SEQ * QKVC, 64,
        out_attn, SEQ, (long long)HEADS * SEQ * SEQ, (long long)SEQ * SEQ,
        64, HEADS, 0.125f, nullptr);

    // 3) softmax in place on out_attn
    softmax_rows<<<(BATCH * HEADS * SEQ) / 8, 256>>>(out_attn);

    // 4) ctx = P @ V (batched), B is [K=m][N=d] n-contig (BL=1)
    gemm3<128,64,32,32,1><<<dim3(1, SEQ/128, BATCH*HEADS), 256, SM_PV>>>(
        out_attn, SEQ, (long long)HEADS * SEQ * SEQ, (long long)SEQ * SEQ,
        qkv_s + 2 * CDIM, QKVC, (long long)SEQ * QKVC, 64,
        ctx_s, CDIM, (long long)SEQ * CDIM, 64,
        SEQ, HEADS, 1.0f, nullptr);

    // 5) proj: ctx @ proj_w^T + bias -> out
    gemm3<128,128,64,32,0><<<dim3(CDIM/128, MTOK/128, 1), 256, SM_BIG>>>(
        ctx_s, CDIM, 0, 0,
        proj_w, CDIM, 0, 0,
        out_proj, CDIM, 0, 0,
        CDIM, 1, 1.0f, proj_b);
}

// round 5
// speedup vs baseline: 2.3416x; 1.1779x over previous
#include <cuda_runtime.h>
#include <cuda_bf16.h>
#include <cstdint>
#include <cstddef>

#define BATCH 8
#define SEQ   1024
#define CDIM  768
#define HEADS 12
#define MTOK  (BATCH*SEQ)      // 8192
#define QKVC  (3*CDIM)         // 2304

// Scratch (device globals — allocation is forbidden)
__device__ float g_qkv[(size_t)MTOK * QKVC];        // [8192, 2304]
__device__ float g_ctx[(size_t)MTOK * CDIM];        // [8192, 768]
__device__ float g_rowsum[(size_t)BATCH * HEADS * SEQ];  // softmax denominators

// ---------------------------------------------------------------------------
__device__ __forceinline__ void mma16816(float* d, const uint32_t* a, const uint32_t* b)
{
    asm volatile(
        "mma.sync.aligned.m16n8k16.row.col.f32.bf16.bf16.f32 "
        "{%0,%1,%2,%3},{%4,%5,%6,%7},{%8,%9},{%0,%1,%2,%3};\n"
        : "+f"(d[0]), "+f"(d[1]), "+f"(d[2]), "+f"(d[3])
        : "r"(a[0]), "r"(a[1]), "r"(a[2]), "r"(a[3]), "r"(b[0]), "r"(b[1]));
}

__device__ __forceinline__ void ldsm_x4(uint32_t* r, uint32_t saddr)
{
    asm volatile("ldmatrix.sync.aligned.m8n8.x4.shared.b16 {%0,%1,%2,%3}, [%4];"
        : "=r"(r[0]), "=r"(r[1]), "=r"(r[2]), "=r"(r[3]) : "r"(saddr));
}

// split fp32 pair -> (hi, mid) bf16x2 pairs
__device__ __forceinline__ void cvt_pair(float x, float y, uint32_t& hi, uint32_t& mid)
{
    __nv_bfloat162 h = __floats2bfloat162_rn(x, y);
    float rx = x - __bfloat162float(__low2bfloat16(h));
    float ry = y - __bfloat162float(__high2bfloat16(h));
    __nv_bfloat162 m = __floats2bfloat162_rn(rx, ry);
    hi  = *reinterpret_cast<uint32_t*>(&h);
    mid = *reinterpret_cast<uint32_t*>(&m);
}

// ---------------------------------------------------------------------------
// Batched GEMM, bf16x3 (hi/mid split, 3 MMAs). C = alpha*A@B^T (+bias).
// BL=0: B [N,K] k-contig. BL=1: B [K,N] n-contig.
// MODE=0: plain epilogue (alpha, bias).
// MODE=1: epilogue writes exp(alpha*acc) and atomically accumulates row sums.
// MODE=2: A-tiles are scaled by 1/rowsum[row] on load and written back to A
//         (in-place softmax normalization fused into the consumer GEMM).
// ---------------------------------------------------------------------------
template<int BM, int BN, int WM, int WN, int BL, int MODE>
__global__ __launch_bounds__(256, 2) void gemm3(
    const float* __restrict__ Abase, int lda, long long sa1, long long sa2,
    const float* __restrict__ Bbase, int ldb, long long sb1, long long sb2,
    float* __restrict__ Cbase, int ldc, long long sc1, long long sc2,
    int K, int nz2, float alpha, const float* __restrict__ bias,
    float* __restrict__ rowsum)
{
    constexpr int BK  = 32;
    constexpr int BKP = 40;                 // padded k-stride (16B-aligned rows for LDSM)
    constexpr int MW  = BM / WM;
    constexpr int MF  = WM / 16;
    constexpr int NF  = WN / 8;
    constexpr int BITER = (BN * BK) / (256 * 4);

    extern __shared__ __nv_bfloat16 sm[];
    __nv_bfloat16* Asm = sm;                       // [2][2][BM][BKP]
    __nv_bfloat16* Bsm = sm + 4 * BM * BKP;        // [2][2][BN][BKP]
#define ASM(bb,s,m,k) Asm[(((bb)*2+(s))*BM + (m))*BKP + (k)]
#define BSM(bb,s,n,k) Bsm[(((bb)*2+(s))*BN + (n))*BKP + (k)]
    const uint32_t asm_u32 = (uint32_t)__cvta_generic_to_shared(Asm);
    const uint32_t bsm_u32 = (uint32_t)__cvta_generic_to_shared(Bsm);

    const int z  = blockIdx.z;
    const int z1 = z / nz2, z2 = z - z1 * nz2;
    const float* A = Abase + (size_t)z1 * sa1 + (size_t)z2 * sa2;
    const float* B = Bbase + (size_t)z1 * sb1 + (size_t)z2 * sb2;
    float*       C = Cbase + (size_t)z1 * sc1 + (size_t)z2 * sc2;
    float* Amut = const_cast<float*>(A);   // MODE==2 write-back

    const int m0  = blockIdx.y * BM;
    const int n0  = blockIdx.x * BN;
    const int tid = threadIdx.x;
    const int w    = tid >> 5, lane = tid & 31;
    const int wm   = w % MW,   wn   = w / MW;
    const int g    = lane >> 2;
    const int t2   = (lane & 3) * 2;

    // ldmatrix per-thread source offsets
    const int a_row_off = ((lane >> 3) & 1) * 8 + (lane & 7);
    const int a_col_off = (lane >> 4) * 8;
    const int b_row_off = (lane >> 4) * 8 + (lane & 7);
    const int b_col_off = ((lane >> 3) & 1) * 8;

    float acc[MF][NF][4];
#pragma unroll
    for (int i = 0; i < MF; i++)
#pragma unroll
        for (int j = 0; j < NF; j++)
#pragma unroll
            for (int q = 0; q < 4; q++) acc[i][j][q] = 0.0f;

    float4 ra[4];
    float4 rb[BITER];

    const int sm_row = tid >> 1;
    const int sm_kq  = (tid & 1) * 16;

    // MODE==2: per-thread row normalizer (row is fixed = m0 + sm_row)
    float anorm = 1.0f;
    if (MODE == 2)
        anorm = 1.0f / rowsum[(size_t)z * SEQ + m0 + sm_row];

#define LOAD_TILE(ktb)                                                          \
    {                                                                           \
        float* Ap = Amut + (size_t)(m0 + sm_row) * lda + (ktb) + sm_kq;         \
        _Pragma("unroll")                                                       \
        for (int ldj = 0; ldj < 4; ldj++)                                       \
            ra[ldj] = *(const float4*)(Ap + 4 * ldj);                           \
        if (MODE == 2) {                                                        \
            _Pragma("unroll")                                                   \
            for (int ldj = 0; ldj < 4; ldj++) {                                 \
                ra[ldj].x *= anorm; ra[ldj].y *= anorm;                         \
                ra[ldj].z *= anorm; ra[ldj].w *= anorm;                         \
                *(float4*)(Ap + 4 * ldj) = ra[ldj];                             \
            }                                                                   \
        }                                                                       \
        _Pragma("unroll")                                                       \
        for (int ldi = 0; ldi < BITER; ldi++) {                                 \
            int idx = (tid + ldi * 256) * 4;                                    \
            if (BL == 0) {                                                      \
                int n = idx / BK, kk = idx % BK;                                \
                rb[ldi] = *(const float4*)(B + (size_t)(n0 + n) * ldb + (ktb) + kk); \
            } else {                                                            \
                int kk = idx / BN, n = idx % BN;                                \
                rb[ldi] = *(const float4*)(B + (size_t)((ktb) + kk) * ldb + n0 + n); \
            }                                                                   \
        }                                                                       \
    }

#define STORE_TILE(bb)                                                          \
    {                                                                           \
        _Pragma("unroll")                                                       \
        for (int stj = 0; stj < 4; stj++) {                                     \
            uint32_t hi, mid;                                                   \
            cvt_pair(ra[stj].x, ra[stj].y, hi, mid);                            \
            *(uint32_t*)&ASM(bb, 0, sm_row, sm_kq + 4 * stj)     = hi;          \
            *(uint32_t*)&ASM(bb, 1, sm_row, sm_kq + 4 * stj)     = mid;         \
            cvt_pair(ra[stj].z, ra[stj].w, hi, mid);                            \
            *(uint32_t*)&ASM(bb, 0, sm_row, sm_kq + 4 * stj + 2) = hi;          \
            *(uint32_t*)&ASM(bb, 1, sm_row, sm_kq + 4 * stj + 2) = mid;         \
        }                                                                       \
        _Pragma("unroll")                                                       \
        for (int sti = 0; sti < BITER; sti++) {                                 \
            int idx = (tid + sti * 256) * 4;                                    \
            if (BL == 0) {                                                      \
                int n = idx / BK, kk = idx % BK;                                \
                uint32_t hi, mid;                                               \
                cvt_pair(rb[sti].x, rb[sti].y, hi, mid);                        \
                *(uint32_t*)&BSM(bb, 0, n, kk)     = hi;                        \
                *(uint32_t*)&BSM(bb, 1, n, kk)     = mid;                       \
                cvt_pair(rb[sti].z, rb[sti].w, hi, mid);                        \
                *(uint32_t*)&BSM(bb, 0, n, kk + 2) = hi;                        \
                *(uint32_t*)&BSM(bb, 1, n, kk + 2) = mid;                       \
            } else {                                                            \
                int kk = idx / BN, n = idx % BN;                                \
                float e[4] = { rb[sti].x, rb[sti].y, rb[sti].z, rb[sti].w };    \
                _Pragma("unroll")                                               \
                for (int q = 0; q < 4; q++) {                                   \
                    __nv_bfloat16 h = __float2bfloat16_rn(e[q]);                \
                    BSM(bb, 0, n + q, kk) = h;                                  \
                    BSM(bb, 1, n + q, kk) =                                     \
                        __float2bfloat16_rn(e[q] - __bfloat162float(h));        \
                }                                                               \
            }                                                                   \
        }                                                                       \
    }

    const int iters = K / BK;

    LOAD_TILE(0);
    STORE_TILE(0);
    __syncthreads();

    for (int it = 0; it < iters; it++) {
        const int buf = it & 1;
        const bool more = (it + 1 < iters);
        if (more) LOAD_TILE((it + 1) * BK);

#pragma unroll
        for (int ks = 0; ks < BK; ks += 16) {
            uint32_t af[2][MF][4], bf[2][NF][2];
#pragma unroll
            for (int s = 0; s < 2; s++) {
#pragma unroll
                for (int i = 0; i < MF; i++) {
                    int row = wm * WM + i * 16 + a_row_off;
                    int col = ks + a_col_off;
                    uint32_t addr = asm_u32 +
                        (uint32_t)((((buf * 2 + s) * BM + row) * BKP + col) * 2);
                    ldsm_x4(af[s][i], addr);
                }
#pragma unroll
                for (int jj = 0; jj < NF / 2; jj++) {
                    int row = wn * WN + jj * 16 + b_row_off;
                    int col = ks + b_col_off;
                    uint32_t addr = bsm_u32 +
                        (uint32_t)((((buf * 2 + s) * BN + row) * BKP + col) * 2);
                    uint32_t r[4];
                    ldsm_x4(r, addr);
                    bf[s][jj * 2 + 0][0] = r[0]; bf[s][jj * 2 + 0][1] = r[1];
                    bf[s][jj * 2 + 1][0] = r[2]; bf[s][jj * 2 + 1][1] = r[3];
                }
            }
#pragma unroll
            for (int i = 0; i < MF; i++)
#pragma unroll
                for (int j = 0; j < NF; j++) {
                    mma16816(acc[i][j], af[0][i], bf[0][j]);   // hi*hi
                    mma16816(acc[i][j], af[0][i], bf[1][j]);   // hi*mid
                    mma16816(acc[i][j], af[1][i], bf[0][j]);   // mid*hi
                }
        }

        if (more) STORE_TILE(buf ^ 1);
        __syncthreads();
    }

    // ---- epilogue ----
    if (MODE == 1) {
        float rs[MF][2];
#pragma unroll
        for (int i = 0; i < MF; i++) { rs[i][0] = 0.0f; rs[i][1] = 0.0f; }
#pragma unroll
        for (int i = 0; i < MF; i++) {
            int r = m0 + wm * WM + i * 16 + g;
#pragma unroll
            for (int j = 0; j < NF; j++) {
                int c = n0 + wn * WN + j * 8 + t2;
                float e0 = __expf(alpha * acc[i][j][0]);
                float e1 = __expf(alpha * acc[i][j][1]);
                float e2 = __expf(alpha * acc[i][j][2]);
                float e3 = __expf(alpha * acc[i][j][3]);
                *(float2*)&C[(size_t)r * ldc + c]       = make_float2(e0, e1);
                *(float2*)&C[(size_t)(r + 8) * ldc + c] = make_float2(e2, e3);
                rs[i][0] += e0 + e1;
                rs[i][1] += e2 + e3;
            }
        }
        // reduce across the 4 lanes sharing a row (lane bits 0-1)
#pragma unroll
        for (int i = 0; i < MF; i++) {
            rs[i][0] += __shfl_xor_sync(0xffffffffu, rs[i][0], 1);
            rs[i][0] += __shfl_xor_sync(0xffffffffu, rs[i][0], 2);
            rs[i][1] += __shfl_xor_sync(0xffffffffu, rs[i][1], 1);
            rs[i][1] += __shfl_xor_sync(0xffffffffu, rs[i][1], 2);
        }
        if ((lane & 3) == 0) {
            size_t base = (size_t)z * SEQ + m0 + wm * WM;
#pragma unroll
            for (int i = 0; i < MF; i++) {
                atomicAdd(&rowsum[base + i * 16 + g],     rs[i][0]);
                atomicAdd(&rowsum[base + i * 16 + 8 + g], rs[i][1]);
            }
        }
    } else {
#pragma unroll
        for (int i = 0; i < MF; i++) {
            int r = m0 + wm * WM + i * 16 + g;
#pragma unroll
            for (int j = 0; j < NF; j++) {
                int c = n0 + wn * WN + j * 8 + t2;
                float b0 = bias ? bias[c]     : 0.0f;
                float b1 = bias ? bias[c + 1] : 0.0f;
                float2 v0 = make_float2(alpha * acc[i][j][0] + b0, alpha * acc[i][j][1] + b1);
                float2 v1 = make_float2(alpha * acc[i][j][2] + b0, alpha * acc[i][j][3] + b1);
                *(float2*)&C[(size_t)r * ldc + c]       = v0;
                *(float2*)&C[(size_t)(r + 8) * ldc + c] = v1;
            }
        }
    }
#undef ASM
#undef BSM
#undef LOAD_TILE
#undef STORE_TILE
}

// ---------------------------------------------------------------------------
__global__ void zero_rowsum(float* __restrict__ rs)
{
    rs[(size_t)blockIdx.x * 1024 + threadIdx.x] = 0.0f;
}

// ---------------------------------------------------------------------------
extern "C" void kernel_launch(void* const* d_in, const int* in_sizes, int n_in,
                              void* d_out, int out_size)
{
    const float* x      = (const float*)d_in[0];   // [8,1024,768]
    const float* qkv_w  = (const float*)d_in[1];   // [2304,768]
    const float* proj_w = (const float*)d_in[2];   // [768,768]
    const float* proj_b = (const float*)d_in[3];   // [768]

    float* out_proj = (float*)d_out;                          // [8,1024,768]
    float* out_attn = (float*)d_out + (size_t)MTOK * CDIM;    // [8,12,1024,1024]

    float* qkv_s = nullptr;
    float* ctx_s = nullptr;
    float* rsum  = nullptr;
    cudaGetSymbolAddress((void**)&qkv_s, g_qkv);
    cudaGetSymbolAddress((void**)&ctx_s, g_ctx);
    cudaGetSymbolAddress((void**)&rsum,  g_rowsum);

    constexpr int BKP = 40;
    constexpr int SM_BIG = 2 * 2 * (128 + 128) * BKP * 2;  // 81920 B
    constexpr int SM_PV  = 2 * 2 * (128 + 64)  * BKP * 2;  // 61440 B

    cudaFuncSetAttribute((const void*)gemm3<128,128,64,32,0,0>,
                         cudaFuncAttributeMaxDynamicSharedMemorySize, SM_BIG);
    cudaFuncSetAttribute((const void*)gemm3<128,128,64,32,0,1>,
                         cudaFuncAttributeMaxDynamicSharedMemorySize, SM_BIG);
    cudaFuncSetAttribute((const void*)gemm3<128,64,32,32,1,2>,
                         cudaFuncAttributeMaxDynamicSharedMemorySize, SM_PV);

    // 0) zero softmax denominators (graph replays need this every launch)
    zero_rowsum<<<BATCH * HEADS, 1024>>>(rsum);

    // 1) QKV GEMM: [8192,768] @ [2304,768]^T -> g_qkv
    gemm3<128,128,64,32,0,0><<<dim3(QKVC/128, MTOK/128, 1), 256, SM_BIG>>>(
        x, CDIM, 0, 0,
        qkv_w, CDIM, 0, 0,
        qkv_s, QKVC, 0, 0,
        CDIM, 1, 1.0f, nullptr, nullptr);

    // 2) E = exp(0.125 * Q @ K^T) -> out_attn, row sums -> g_rowsum
    gemm3<128,128,64,32,0,1><<<dim3(SEQ/128, SEQ/128, BATCH*HEADS), 256, SM_BIG>>>(
        qkv_s,        QKVC, (long long)SEQ * QKVC, 64,
        qkv_s + CDIM, QKVC, (long long)SEQ * QKVC, 64,
        out_attn, SEQ, (long long)HEADS * SEQ * SEQ, (long long)SEQ * SEQ,
        64, HEADS, 0.125f, nullptr, rsum);

    // 3) ctx = P @ V; normalizes E -> P in place (writes attn output) on load
    gemm3<128,64,32,32,1,2><<<dim3(1, SEQ/128, BATCH*HEADS), 256, SM_PV>>>(
        out_attn, SEQ, (long long)HEADS * SEQ * SEQ, (long long)SEQ * SEQ,
        qkv_s + 2 * CDIM, QKVC, (long long)SEQ * QKVC, 64,
        ctx_s, CDIM, (long long)SEQ * CDIM, 64,
        SEQ, HEADS, 1.0f, nullptr, rsum);

    // 4) proj: ctx @ proj_w^T + bias -> out
    gemm3<128,128,64,32,0,0><<<dim3(CDIM/128, MTOK/128, 1), 256, SM_BIG>>>(
        ctx_s, CDIM, 0, 0,
        proj_w, CDIM, 0, 0,
        out_proj, CDIM, 0, 0,
        CDIM, 1, 1.0f, proj_b, nullptr);
}

// round 7
// speedup vs baseline: 2.5506x; 1.0892x over previous
#include <cuda_runtime.h>
#include <cuda_bf16.h>
#include <cstdint>
#include <cstddef>

#define BATCH 8
#define SEQ   1024
#define CDIM  768
#define HEADS 12
#define MTOK  (BATCH*SEQ)      // 8192
#define QKVC  (3*CDIM)         // 2304

// Persistent scratch (device globals — allocation is forbidden)
__device__ __nv_bfloat16 g_x_hi   [(size_t)MTOK * CDIM];
__device__ __nv_bfloat16 g_x_mid  [(size_t)MTOK * CDIM];
__device__ __nv_bfloat16 g_wqkv_hi [(size_t)QKVC * CDIM];
__device__ __nv_bfloat16 g_wqkv_mid[(size_t)QKVC * CDIM];
__device__ __nv_bfloat16 g_wproj_hi [(size_t)CDIM * CDIM];
__device__ __nv_bfloat16 g_wproj_mid[(size_t)CDIM * CDIM];
__device__ __nv_bfloat16 g_qkv_hi [(size_t)MTOK * QKVC];
__device__ __nv_bfloat16 g_qkv_mid[(size_t)MTOK * QKVC];
__device__ __nv_bfloat16 g_ctx_hi [(size_t)MTOK * CDIM];
__device__ __nv_bfloat16 g_ctx_mid[(size_t)MTOK * CDIM];
__device__ float g_rowsum[(size_t)BATCH * HEADS * SEQ];

// ---------------------------------------------------------------------------
__device__ __forceinline__ void mma16816(float* d, const uint32_t* a, const uint32_t* b)
{
    asm volatile(
        "mma.sync.aligned.m16n8k16.row.col.f32.bf16.bf16.f32 "
        "{%0,%1,%2,%3},{%4,%5,%6,%7},{%8,%9},{%0,%1,%2,%3};\n"
        : "+f"(d[0]), "+f"(d[1]), "+f"(d[2]), "+f"(d[3])
        : "r"(a[0]), "r"(a[1]), "r"(a[2]), "r"(a[3]), "r"(b[0]), "r"(b[1]));
}

__device__ __forceinline__ void ldsm_x4(uint32_t* r, uint32_t saddr)
{
    asm volatile("ldmatrix.sync.aligned.m8n8.x4.shared.b16 {%0,%1,%2,%3}, [%4];"
        : "=r"(r[0]), "=r"(r[1]), "=r"(r[2]), "=r"(r[3]) : "r"(saddr));
}

__device__ __forceinline__ void ldsm_x4_t(uint32_t* r, uint32_t saddr)
{
    asm volatile("ldmatrix.sync.aligned.m8n8.x4.trans.shared.b16 {%0,%1,%2,%3}, [%4];"
        : "=r"(r[0]), "=r"(r[1]), "=r"(r[2]), "=r"(r[3]) : "r"(saddr));
}

__device__ __forceinline__ void cvt_pair(float x, float y, uint32_t& hi, uint32_t& mid)
{
    __nv_bfloat162 h = __floats2bfloat162_rn(x, y);
    float rx = x - __bfloat162float(__low2bfloat16(h));
    float ry = y - __bfloat162float(__high2bfloat16(h));
    __nv_bfloat162 m = __floats2bfloat162_rn(rx, ry);
    hi  = *reinterpret_cast<uint32_t*>(&h);
    mid = *reinterpret_cast<uint32_t*>(&m);
}

// ---------------------------------------------------------------------------
// Split fp32 -> hi/mid bf16 planes (vectorized by 4)
// ---------------------------------------------------------------------------
__global__ __launch_bounds__(256) void split_f32(
    const float* __restrict__ src, __nv_bfloat16* __restrict__ hi,
    __nv_bfloat16* __restrict__ mid, int n4)
{
    int i = blockIdx.x * blockDim.x + threadIdx.x;
    if (i >= n4) return;
    float4 v = ((const float4*)src)[i];
    uint32_t h0, m0, h1, m1;
    cvt_pair(v.x, v.y, h0, m0);
    cvt_pair(v.z, v.w, h1, m1);
    ((uint2*)hi)[i]  = make_uint2(h0, h1);
    ((uint2*)mid)[i] = make_uint2(m0, m1);
}

__global__ void zero_rowsum(float* __restrict__ rs)
{
    rs[(size_t)blockIdx.x * 1024 + threadIdx.x] = 0.0f;
}

// ---------------------------------------------------------------------------
// Batched GEMM on pre-split bf16 hi/mid operands. 3 MMAs (hh, hm, mh).
// ASRC=0:  A from (Ahi,Amid) [M,K] k-contig  — pure vector staging.
// ASRC=1:  A from Af32 (attn E values): normalize by 1/rowsum, write back
//          normalized P in place, split to hi/mid in smem. (PV kernel)
// BTRANS=0: B from (Bhi,Bmid) [N,K] k-contig, ldmatrix.  (BN must be 128)
// BTRANS=1: B from (Bhi,Bmid) [K,N] n-contig, ldmatrix.trans. (BN=64)
// OUT=0: C fp32 = acc + bias.  OUT=1: C fp32 = exp(alpha*acc), rowsum atomics.
// OUT=2: C split to (Chi,Cmid) planes.
// ---------------------------------------------------------------------------
template<int BM, int BN, int WM, int WN, int ASRC, int BTRANS, int OUT>
__global__ __launch_bounds__(256, 2) void gemm3(
    const __nv_bfloat16* __restrict__ Ahi, const __nv_bfloat16* __restrict__ Amid,
    float* __restrict__ Af32, int lda, long long sa1, long long sa2,
    const __nv_bfloat16* __restrict__ Bhi, const __nv_bfloat16* __restrict__ Bmid,
    int ldb, long long sb1, long long sb2,
    float* __restrict__ Cf, __nv_bfloat16* __restrict__ Chi, __nv_bfloat16* __restrict__ Cmid,
    int ldc, long long sc1, long long sc2,
    int K, int nz2, float alpha, const float* __restrict__ bias,
    float* __restrict__ rowsum)
{
    constexpr int BK  = 32;
    constexpr int BKP = 40;       // A / B(k-contig) row stride (bf16 elems)
    constexpr int BNP = 72;       // B(trans) row stride
    constexpr int MW  = BM / WM;
    constexpr int MF  = WM / 16;
    constexpr int NF  = WN / 8;

    extern __shared__ __nv_bfloat16 sm[];
    __nv_bfloat16* Asm = sm;                         // [2][2][BM][BKP]
    __nv_bfloat16* Bsm = sm + 4 * BM * BKP;          // k-contig: [2][2][BN][BKP] / trans: [2][2][BK][BNP]
#define ASM(bb,s,m,k)  Asm[(((bb)*2+(s))*BM + (m))*BKP + (k)]
#define BSM(bb,s,n,k)  Bsm[(((bb)*2+(s))*BN + (n))*BKP + (k)]
#define BSMT(bb,s,k,n) Bsm[(((bb)*2+(s))*BK + (k))*BNP + (n)]
    const uint32_t asm_u32 = (uint32_t)__cvta_generic_to_shared(Asm);
    const uint32_t bsm_u32 = (uint32_t)__cvta_generic_to_shared(Bsm);

    const int z  = blockIdx.z;
    const int z1 = z / nz2, z2 = z - z1 * nz2;
    const long long zofA = z1 * sa1 + z2 * sa2;
    const long long zofB = z1 * sb1 + z2 * sb2;
    const long long zofC = z1 * sc1 + z2 * sc2;

    const int m0  = blockIdx.y * BM;
    const int n0  = blockIdx.x * BN;
    const int tid = threadIdx.x;
    const int w    = tid >> 5, lane = tid & 31;
    const int wm   = w % MW,   wn   = w / MW;
    const int g    = lane >> 2;
    const int t2   = (lane & 3) * 2;

    // ldmatrix per-thread source offsets.
    // A fragments (m16 x k16): matrices ordered {m0k0, m8k0, m0k8, m8k8}
    const int a_row_off = ((lane >> 3) & 1) * 8 + (lane & 7);
    const int a_col_off = (lane >> 4) * 8;
    // B fragments k-contig (n16 x k16): matrices MUST be {n0k0, n0k8, n8k0, n8k8}
    // (R6 bug: used A-style offsets here -> k8/n8 fragments swapped)
    const int b_row_off = (lane >> 4) * 8 + (lane & 7);
    const int b_col_off = ((lane >> 3) & 1) * 8;
    // trans-B offsets ([K][N] tile, rows = k): {k0n0, k8n0, k0n8, k8n8}
    const int bt_k_off = ((lane >> 3) & 1) * 8 + (lane & 7);
    const int bt_n_off = (lane >> 4) * 8;

    float acc[MF][NF][4];
#pragma unroll
    for (int i = 0; i < MF; i++)
#pragma unroll
        for (int j = 0; j < NF; j++)
#pragma unroll
            for (int q = 0; q < 4; q++) acc[i][j][q] = 0.0f;

    // ---- staging state ----
    const int a_row = tid >> 1;            // 0..127  (BM=128 always)
    const int a_seg = (tid & 1) * 16;      // element offset within BK
    uint4 rah[2], ram[2];                  // bf16 A staging
    float4 raf[4];                         // fp32 A staging (ASRC=1)
    uint4 rbh[2], rbm[2];                  // B staging
    const int bt_k  = tid >> 3;            // 0..31
    const int bt_sg = (tid & 7) * 8;       // 0..56

    float anorm = 1.0f;
    if (ASRC == 1)
        anorm = 1.0f / rowsum[(size_t)z * SEQ + m0 + a_row];

    auto load_tile = [&](int kt) {
        if (ASRC == 0) {
            const __nv_bfloat16* ph = Ahi + zofA + (size_t)(m0 + a_row) * lda + kt + a_seg;
            const __nv_bfloat16* pm = Amid + zofA + (size_t)(m0 + a_row) * lda + kt + a_seg;
            rah[0] = *(const uint4*)ph;       rah[1] = *(const uint4*)(ph + 8);
            ram[0] = *(const uint4*)pm;       ram[1] = *(const uint4*)(pm + 8);
        } else {
            float* Ap = Af32 + zofA + (size_t)(m0 + a_row) * lda + kt + a_seg;
#pragma unroll
            for (int q = 0; q < 4; q++) {
                raf[q] = *(const float4*)(Ap + 4 * q);
                raf[q].x *= anorm; raf[q].y *= anorm;
                raf[q].z *= anorm; raf[q].w *= anorm;
                *(float4*)(Ap + 4 * q) = raf[q];   // write back normalized P (attn output)
            }
        }
        if (BTRANS == 0) {
            const __nv_bfloat16* ph = Bhi + zofB + (size_t)(n0 + a_row) * ldb + kt + a_seg;
            const __nv_bfloat16* pm = Bmid + zofB + (size_t)(n0 + a_row) * ldb + kt + a_seg;
            rbh[0] = *(const uint4*)ph;       rbh[1] = *(const uint4*)(ph + 8);
            rbm[0] = *(const uint4*)pm;       rbm[1] = *(const uint4*)(pm + 8);
        } else {
            const __nv_bfloat16* ph = Bhi + zofB + (size_t)(kt + bt_k) * ldb + n0 + bt_sg;
            const __nv_bfloat16* pm = Bmid + zofB + (size_t)(kt + bt_k) * ldb + n0 + bt_sg;
            rbh[0] = *(const uint4*)ph;
            rbm[0] = *(const uint4*)pm;
        }
    };

    auto store_tile = [&](int bb) {
        if (ASRC == 0) {
            *(uint4*)&ASM(bb, 0, a_row, a_seg)     = rah[0];
            *(uint4*)&ASM(bb, 0, a_row, a_seg + 8) = rah[1];
            *(uint4*)&ASM(bb, 1, a_row, a_seg)     = ram[0];
            *(uint4*)&ASM(bb, 1, a_row, a_seg + 8) = ram[1];
        } else {
#pragma unroll
            for (int q = 0; q < 4; q++) {
                uint32_t hi, mid;
                cvt_pair(raf[q].x, raf[q].y, hi, mid);
                *(uint32_t*)&ASM(bb, 0, a_row, a_seg + 4 * q)     = hi;
                *(uint32_t*)&ASM(bb, 1, a_row, a_seg + 4 * q)     = mid;
                cvt_pair(raf[q].z, raf[q].w, hi, mid);
                *(uint32_t*)&ASM(bb, 0, a_row, a_seg + 4 * q + 2) = hi;
                *(uint32_t*)&ASM(bb, 1, a_row, a_seg + 4 * q + 2) = mid;
            }
        }
        if (BTRANS == 0) {
            *(uint4*)&BSM(bb, 0, a_row, a_seg)     = rbh[0];
            *(uint4*)&BSM(bb, 0, a_row, a_seg + 8) = rbh[1];
            *(uint4*)&BSM(bb, 1, a_row, a_seg)     = rbm[0];
            *(uint4*)&BSM(bb, 1, a_row, a_seg + 8) = rbm[1];
        } else {
            *(uint4*)&BSMT(bb, 0, bt_k, bt_sg) = rbh[0];
            *(uint4*)&BSMT(bb, 1, bt_k, bt_sg) = rbm[0];
        }
    };

    const int iters = K / BK;

    load_tile(0);
    store_tile(0);
    __syncthreads();

    for (int it = 0; it < iters; it++) {
        const int buf = it & 1;
        const bool more = (it + 1 < iters);
        if (more) load_tile((it + 1) * BK);

#pragma unroll
        for (int ks = 0; ks < BK; ks += 16) {
            uint32_t af[2][MF][4], bf[2][NF][2];
#pragma unroll
            for (int s = 0; s < 2; s++) {
#pragma unroll
                for (int i = 0; i < MF; i++) {
                    int row = wm * WM + i * 16 + a_row_off;
                    int col = ks + a_col_off;
                    uint32_t addr = asm_u32 +
                        (uint32_t)((((buf * 2 + s) * BM + row) * BKP + col) * 2);
                    ldsm_x4(af[s][i], addr);
                }
#pragma unroll
                for (int jj = 0; jj < NF / 2; jj++) {
                    uint32_t r[4];
                    if (BTRANS == 0) {
                        int row = wn * WN + jj * 16 + b_row_off;
                        int col = ks + b_col_off;
                        uint32_t addr = bsm_u32 +
                            (uint32_t)((((buf * 2 + s) * BN + row) * BKP + col) * 2);
                        ldsm_x4(r, addr);
                    } else {
                        int kR = ks + bt_k_off;
                        int nB = wn * WN + jj * 16 + bt_n_off;
                        uint32_t addr = bsm_u32 +
                            (uint32_t)((((buf * 2 + s) * BK + kR) * BNP + nB) * 2);
                        ldsm_x4_t(r, addr);
                    }
                    bf[s][jj * 2 + 0][0] = r[0]; bf[s][jj * 2 + 0][1] = r[1];
                    bf[s][jj * 2 + 1][0] = r[2]; bf[s][jj * 2 + 1][1] = r[3];
                }
            }
#pragma unroll
            for (int i = 0; i < MF; i++)
#pragma unroll
                for (int j = 0; j < NF; j++) {
                    mma16816(acc[i][j], af[0][i], bf[0][j]);   // hi*hi
                    mma16816(acc[i][j], af[0][i], bf[1][j]);   // hi*mid
                    mma16816(acc[i][j], af[1][i], bf[0][j]);   // mid*hi
                }
        }

        if (more) store_tile(buf ^ 1);
        __syncthreads();
    }

    // ---- epilogue ----
    if (OUT == 1) {
        float* C = Cf + zofC;
        float rs[MF][2];
#pragma unroll
        for (int i = 0; i < MF; i++) { rs[i][0] = 0.0f; rs[i][1] = 0.0f; }
#pragma unroll
        for (int i = 0; i < MF; i++) {
            int r = m0 + wm * WM + i * 16 + g;
#pragma unroll
            for (int j = 0; j < NF; j++) {
                int c = n0 + wn * WN + j * 8 + t2;
                float e0 = __expf(alpha * acc[i][j][0]);
                float e1 = __expf(alpha * acc[i][j][1]);
                float e2 = __expf(alpha * acc[i][j][2]);
                float e3 = __expf(alpha * acc[i][j][3]);
                *(float2*)&C[(size_t)r * ldc + c]       = make_float2(e0, e1);
                *(float2*)&C[(size_t)(r + 8) * ldc + c] = make_float2(e2, e3);
                rs[i][0] += e0 + e1;
                rs[i][1] += e2 + e3;
            }
        }
#pragma unroll
        for (int i = 0; i < MF; i++) {
            rs[i][0] += __shfl_xor_sync(0xffffffffu, rs[i][0], 1);
            rs[i][0] += __shfl_xor_sync(0xffffffffu, rs[i][0], 2);
            rs[i][1] += __shfl_xor_sync(0xffffffffu, rs[i][1], 1);
            rs[i][1] += __shfl_xor_sync(0xffffffffu, rs[i][1], 2);
        }
        if ((lane & 3) == 0) {
            size_t base = (size_t)z * SEQ + m0 + wm * WM;
#pragma unroll
            for (int i = 0; i < MF; i++) {
                atomicAdd(&rowsum[base + i * 16 + g],     rs[i][0]);
                atomicAdd(&rowsum[base + i * 16 + 8 + g], rs[i][1]);
            }
        }
    } else if (OUT == 2) {
        __nv_bfloat16* Ch = Chi + zofC;
        __nv_bfloat16* Cm = Cmid + zofC;
#pragma unroll
        for (int i = 0; i < MF; i++) {
            int r = m0 + wm * WM + i * 16 + g;
#pragma unroll
            for (int j = 0; j < NF; j++) {
                int c = n0 + wn * WN + j * 8 + t2;
                uint32_t h, mm;
                cvt_pair(acc[i][j][0], acc[i][j][1], h, mm);
                *(uint32_t*)&Ch[(size_t)r * ldc + c] = h;
                *(uint32_t*)&Cm[(size_t)r * ldc + c] = mm;
                cvt_pair(acc[i][j][2], acc[i][j][3], h, mm);
                *(uint32_t*)&Ch[(size_t)(r + 8) * ldc + c] = h;
                *(uint32_t*)&Cm[(size_t)(r + 8) * ldc + c] = mm;
            }
        }
    } else {
        float* C = Cf + zofC;
#pragma unroll
        for (int i = 0; i < MF; i++) {
            int r = m0 + wm * WM + i * 16 + g;
#pragma unroll
            for (int j = 0; j < NF; j++) {
                int c = n0 + wn * WN + j * 8 + t2;
                float b0 = bias ? bias[c]     : 0.0f;
                float b1 = bias ? bias[c + 1] : 0.0f;
                *(float2*)&C[(size_t)r * ldc + c] =
                    make_float2(acc[i][j][0] + b0, acc[i][j][1] + b1);
                *(float2*)&C[(size_t)(r + 8) * ldc + c] =
                    make_float2(acc[i][j][2] + b0, acc[i][j][3] + b1);
            }
        }
    }
#undef ASM
#undef BSM
#undef BSMT
}

// ---------------------------------------------------------------------------
extern "C" void kernel_launch(void* const* d_in, const int* in_sizes, int n_in,
                              void* d_out, int out_size)
{
    const float* x      = (const float*)d_in[0];   // [8,1024,768]
    const float* qkv_w  = (const float*)d_in[1];   // [2304,768]
    const float* proj_w = (const float*)d_in[2];   // [768,768]
    const float* proj_b = (const float*)d_in[3];   // [768]

    float* out_proj = (float*)d_out;                          // [8,1024,768]
    float* out_attn = (float*)d_out + (size_t)MTOK * CDIM;    // [8,12,1024,1024]

    __nv_bfloat16 *x_hi, *x_mid, *wq_hi, *wq_mid, *wp_hi, *wp_mid;
    __nv_bfloat16 *qkv_hi, *qkv_mid, *ctx_hi, *ctx_mid;
    float* rsum;
    cudaGetSymbolAddress((void**)&x_hi,   g_x_hi);
    cudaGetSymbolAddress((void**)&x_mid,  g_x_mid);
    cudaGetSymbolAddress((void**)&wq_hi,  g_wqkv_hi);
    cudaGetSymbolAddress((void**)&wq_mid, g_wqkv_mid);
    cudaGetSymbolAddress((void**)&wp_hi,  g_wproj_hi);
    cudaGetSymbolAddress((void**)&wp_mid, g_wproj_mid);
    cudaGetSymbolAddress((void**)&qkv_hi, g_qkv_hi);
    cudaGetSymbolAddress((void**)&qkv_mid,g_qkv_mid);
    cudaGetSymbolAddress((void**)&ctx_hi, g_ctx_hi);
    cudaGetSymbolAddress((void**)&ctx_mid,g_ctx_mid);
    cudaGetSymbolAddress((void**)&rsum,   g_rowsum);

    constexpr int BKP = 40, BNP = 72;
    constexpr int SM_KC = (4 * 128 * BKP + 4 * 128 * BKP) * 2;   // 81920 B
    constexpr int SM_TR = (4 * 128 * BKP + 4 * 32 * BNP) * 2;    // 59392 B

    cudaFuncSetAttribute((const void*)gemm3<128,128,64,32,0,0,2>,
                         cudaFuncAttributeMaxDynamicSharedMemorySize, SM_KC);
    cudaFuncSetAttribute((const void*)gemm3<128,128,64,32,0,0,1>,
                         cudaFuncAttributeMaxDynamicSharedMemorySize, SM_KC);
    cudaFuncSetAttribute((const void*)gemm3<128,64,32,32,1,1,2>,
                         cudaFuncAttributeMaxDynamicSharedMemorySize, SM_TR);
    cudaFuncSetAttribute((const void*)gemm3<128,128,64,32,0,0,0>,
                         cudaFuncAttributeMaxDynamicSharedMemorySize, SM_KC);

    // 0) split inputs to bf16 hi/mid planes + zero rowsums
    split_f32<<<(MTOK * CDIM / 4 + 255) / 256, 256>>>(x, x_hi, x_mid, MTOK * CDIM / 4);
    split_f32<<<(QKVC * CDIM / 4 + 255) / 256, 256>>>(qkv_w, wq_hi, wq_mid, QKVC * CDIM / 4);
    split_f32<<<(CDIM * CDIM / 4 + 255) / 256, 256>>>(proj_w, wp_hi, wp_mid, CDIM * CDIM / 4);
    zero_rowsum<<<BATCH * HEADS, 1024>>>(rsum);

    // 1) QKV GEMM -> split planes g_qkv
    gemm3<128,128,64,32,0,0,2><<<dim3(QKVC/128, MTOK/128, 1), 256, SM_KC>>>(
        x_hi, x_mid, nullptr, CDIM, 0, 0,
        wq_hi, wq_mid, CDIM, 0, 0,
        nullptr, qkv_hi, qkv_mid, QKVC, 0, 0,
        CDIM, 1, 1.0f, nullptr, rsum);

    // 2) E = exp(0.125 * Q @ K^T) -> out_attn (fp32), rowsums
    gemm3<128,128,64,32,0,0,1><<<dim3(SEQ/128, SEQ/128, BATCH*HEADS), 256, SM_KC>>>(
        qkv_hi, qkv_mid, nullptr, QKVC, (long long)SEQ * QKVC, 64,
        qkv_hi + CDIM, qkv_mid + CDIM, QKVC, (long long)SEQ * QKVC, 64,
        out_attn, nullptr, nullptr, SEQ,
        (long long)HEADS * SEQ * SEQ, (long long)SEQ * SEQ,
        64, HEADS, 0.125f, nullptr, rsum);

    // 3) ctx = P @ V; normalizes E->P in place (attn output), V via ldmatrix.trans
    gemm3<128,64,32,32,1,1,2><<<dim3(1, SEQ/128, BATCH*HEADS), 256, SM_TR>>>(
        nullptr, nullptr, out_attn, SEQ,
        (long long)HEADS * SEQ * SEQ, (long long)SEQ * SEQ,
        qkv_hi + 2 * CDIM, qkv_mid + 2 * CDIM, QKVC, (long long)SEQ * QKVC, 64,
        nullptr, ctx_hi, ctx_mid, CDIM, (long long)SEQ * CDIM, 64,
        SEQ, HEADS, 1.0f, nullptr, rsum);

    // 4) proj: ctx @ proj_w^T + bias -> out (fp32)
    gemm3<128,128,64,32,0,0,0><<<dim3(CDIM/128, MTOK/128, 1), 256, SM_KC>>>(
        ctx_hi, ctx_mid, nullptr, CDIM, 0, 0,
        wp_hi, wp_mid, CDIM, 0, 0,
        out_proj, nullptr, nullptr, CDIM, 0, 0,
        CDIM, 1, 1.0f, proj_b, rsum);
}

// round 8
// speedup vs baseline: 2.7886x; 1.0933x over previous
#include <cuda_runtime.h>
#include <cuda_bf16.h>
#include <cstdint>
#include <cstddef>

#define BATCH 8
#define SEQ   1024
#define CDIM  768
#define HEADS 12
#define MTOK  (BATCH*SEQ)      // 8192
#define QKVC  (3*CDIM)         // 2304

// Persistent scratch (device globals — allocation is forbidden)
__device__ __nv_bfloat16 g_x_hi   [(size_t)MTOK * CDIM];
__device__ __nv_bfloat16 g_x_mid  [(size_t)MTOK * CDIM];
__device__ __nv_bfloat16 g_wqkv_hi [(size_t)QKVC * CDIM];
__device__ __nv_bfloat16 g_wqkv_mid[(size_t)QKVC * CDIM];
__device__ __nv_bfloat16 g_wproj_hi [(size_t)CDIM * CDIM];
__device__ __nv_bfloat16 g_wproj_mid[(size_t)CDIM * CDIM];
__device__ __nv_bfloat16 g_qkv_hi [(size_t)MTOK * QKVC];
__device__ __nv_bfloat16 g_qkv_mid[(size_t)MTOK * QKVC];
__device__ __nv_bfloat16 g_ctx_hi [(size_t)MTOK * CDIM];
__device__ __nv_bfloat16 g_ctx_mid[(size_t)MTOK * CDIM];
__device__ float g_rowsum[(size_t)BATCH * HEADS * SEQ];

// ---------------------------------------------------------------------------
__device__ __forceinline__ void mma16816(float* d, const uint32_t* a, const uint32_t* b)
{
    asm volatile(
        "mma.sync.aligned.m16n8k16.row.col.f32.bf16.bf16.f32 "
        "{%0,%1,%2,%3},{%4,%5,%6,%7},{%8,%9},{%0,%1,%2,%3};\n"
        : "+f"(d[0]), "+f"(d[1]), "+f"(d[2]), "+f"(d[3])
        : "r"(a[0]), "r"(a[1]), "r"(a[2]), "r"(a[3]), "r"(b[0]), "r"(b[1]));
}

__device__ __forceinline__ void ldsm_x4(uint32_t* r, uint32_t saddr)
{
    asm volatile("ldmatrix.sync.aligned.m8n8.x4.shared.b16 {%0,%1,%2,%3}, [%4];"
        : "=r"(r[0]), "=r"(r[1]), "=r"(r[2]), "=r"(r[3]) : "r"(saddr));
}

__device__ __forceinline__ void ldsm_x4_t(uint32_t* r, uint32_t saddr)
{
    asm volatile("ldmatrix.sync.aligned.m8n8.x4.trans.shared.b16 {%0,%1,%2,%3}, [%4];"
        : "=r"(r[0]), "=r"(r[1]), "=r"(r[2]), "=r"(r[3]) : "r"(saddr));
}

__device__ __forceinline__ void cp_async16(uint32_t saddr, const void* gptr)
{
    asm volatile("cp.async.cg.shared.global [%0], [%1], 16;"
        :: "r"(saddr), "l"(gptr));
}
#define CP_COMMIT() asm volatile("cp.async.commit_group;" ::: "memory")
#define CP_WAIT0()  asm volatile("cp.async.wait_group 0;" ::: "memory")

__device__ __forceinline__ void cvt_pair(float x, float y, uint32_t& hi, uint32_t& mid)
{
    __nv_bfloat162 h = __floats2bfloat162_rn(x, y);
    float rx = x - __bfloat162float(__low2bfloat16(h));
    float ry = y - __bfloat162float(__high2bfloat16(h));
    __nv_bfloat162 m = __floats2bfloat162_rn(rx, ry);
    hi  = *reinterpret_cast<uint32_t*>(&h);
    mid = *reinterpret_cast<uint32_t*>(&m);
}

// ---------------------------------------------------------------------------
// Fused prep: split x/wqkv/wproj into hi/mid planes + zero rowsums. One launch.
// ---------------------------------------------------------------------------
#define N4_X   (MTOK * CDIM / 4)
#define N4_WQ  (QKVC * CDIM / 4)
#define N4_WP  (CDIM * CDIM / 4)
#define N4_RS  (BATCH * HEADS * SEQ / 4)

__global__ __launch_bounds__(256) void prep_kernel(
    const float* __restrict__ x, const float* __restrict__ wq,
    const float* __restrict__ wp,
    __nv_bfloat16* __restrict__ x_hi, __nv_bfloat16* __restrict__ x_mid,
    __nv_bfloat16* __restrict__ wq_hi, __nv_bfloat16* __restrict__ wq_mid,
    __nv_bfloat16* __restrict__ wp_hi, __nv_bfloat16* __restrict__ wp_mid,
    float* __restrict__ rs)
{
    int i = blockIdx.x * blockDim.x + threadIdx.x;
    const float* src; __nv_bfloat16 *hi, *mid; int off;
    if (i < N4_X)                        { src = x;  hi = x_hi;  mid = x_mid;  off = 0; }
    else if (i < N4_X + N4_WQ)           { src = wq; hi = wq_hi; mid = wq_mid; off = N4_X; }
    else if (i < N4_X + N4_WQ + N4_WP)   { src = wp; hi = wp_hi; mid = wp_mid; off = N4_X + N4_WQ; }
    else if (i < N4_X + N4_WQ + N4_WP + N4_RS) {
        ((float4*)rs)[i - (N4_X + N4_WQ + N4_WP)] = make_float4(0.f, 0.f, 0.f, 0.f);
        return;
    } else return;
    int j = i - off;
    float4 v = ((const float4*)src)[j];
    uint32_t h0, m0, h1, m1;
    cvt_pair(v.x, v.y, h0, m0);
    cvt_pair(v.z, v.w, h1, m1);
    ((uint2*)hi)[j]  = make_uint2(h0, h1);
    ((uint2*)mid)[j] = make_uint2(m0, m1);
}

// ---------------------------------------------------------------------------
// Batched GEMM on pre-split bf16 hi/mid operands. 3 MMAs (hh, hm, mh).
// cp.async staging with load-ahead: issue tile it+1 before computing tile it,
// wait after compute. ASRC=1 keeps the manual fp32 normalize path (PV).
// ---------------------------------------------------------------------------
template<int BM, int BN, int WM, int WN, int ASRC, int BTRANS, int OUT>
__global__ __launch_bounds__(256, 2) void gemm3(
    const __nv_bfloat16* __restrict__ Ahi, const __nv_bfloat16* __restrict__ Amid,
    float* __restrict__ Af32, int lda, long long sa1, long long sa2,
    const __nv_bfloat16* __restrict__ Bhi, const __nv_bfloat16* __restrict__ Bmid,
    int ldb, long long sb1, long long sb2,
    float* __restrict__ Cf, __nv_bfloat16* __restrict__ Chi, __nv_bfloat16* __restrict__ Cmid,
    int ldc, long long sc1, long long sc2,
    int K, int nz2, float alpha, const float* __restrict__ bias,
    float* __restrict__ rowsum)
{
    constexpr int BK  = 32;
    constexpr int BKP = 40;       // A / B(k-contig) row stride (bf16 elems), 80B = 16B-aligned
    constexpr int BNP = 72;       // B(trans) row stride, 144B = 16B-aligned
    constexpr int MW  = BM / WM;
    constexpr int MF  = WM / 16;
    constexpr int NF  = WN / 8;

    extern __shared__ __nv_bfloat16 sm[];
    __nv_bfloat16* Asm = sm;                         // [2][2][BM][BKP]
    __nv_bfloat16* Bsm = sm + 4 * BM * BKP;
#define ASM(bb,s,m,k)  Asm[(((bb)*2+(s))*BM + (m))*BKP + (k)]
#define BSM(bb,s,n,k)  Bsm[(((bb)*2+(s))*BN + (n))*BKP + (k)]
#define BSMT(bb,s,k,n) Bsm[(((bb)*2+(s))*BK + (k))*BNP + (n)]
    const uint32_t asm_u32 = (uint32_t)__cvta_generic_to_shared(Asm);
    const uint32_t bsm_u32 = (uint32_t)__cvta_generic_to_shared(Bsm);

    const int z  = blockIdx.z;
    const int z1 = z / nz2, z2 = z - z1 * nz2;
    const long long zofA = z1 * sa1 + z2 * sa2;
    const long long zofB = z1 * sb1 + z2 * sb2;
    const long long zofC = z1 * sc1 + z2 * sc2;

    const int m0  = blockIdx.y * BM;
    const int n0  = blockIdx.x * BN;
    const int tid = threadIdx.x;
    const int w    = tid >> 5, lane = tid & 31;
    const int wm   = w % MW,   wn   = w / MW;
    const int g    = lane >> 2;
    const int t2   = (lane & 3) * 2;

    // ldmatrix lane offsets (proven mappings — do not touch)
    const int a_row_off = ((lane >> 3) & 1) * 8 + (lane & 7);
    const int a_col_off = (lane >> 4) * 8;
    const int b_row_off = (lane >> 4) * 8 + (lane & 7);
    const int b_col_off = ((lane >> 3) & 1) * 8;
    const int bt_k_off = ((lane >> 3) & 1) * 8 + (lane & 7);
    const int bt_n_off = (lane >> 4) * 8;

    float acc[MF][NF][4];
#pragma unroll
    for (int i = 0; i < MF; i++)
#pragma unroll
        for (int j = 0; j < NF; j++)
#pragma unroll
            for (int q = 0; q < 4; q++) acc[i][j][q] = 0.0f;

    // ---- staging indices ----
    const int a_row = tid >> 1;            // 0..127
    const int a_seg = (tid & 1) * 16;
    const int bt_k  = tid >> 3;            // 0..31
    const int bt_sg = (tid & 7) * 8;

    float anorm = 1.0f;
    if (ASRC == 1)
        anorm = 1.0f / rowsum[(size_t)z * SEQ + m0 + a_row];

    // issue all copies for k-tile kt into buffer bb
    auto issue_tile = [&](int kt, int bb) {
        if (ASRC == 0) {
            const __nv_bfloat16* ph = Ahi + zofA + (size_t)(m0 + a_row) * lda + kt + a_seg;
            const __nv_bfloat16* pm = Amid + zofA + (size_t)(m0 + a_row) * lda + kt + a_seg;
            uint32_t d0 = asm_u32 + (uint32_t)((((bb * 2 + 0) * BM + a_row) * BKP + a_seg) * 2);
            uint32_t d1 = asm_u32 + (uint32_t)((((bb * 2 + 1) * BM + a_row) * BKP + a_seg) * 2);
            cp_async16(d0,      ph);
            cp_async16(d0 + 16, ph + 8);
            cp_async16(d1,      pm);
            cp_async16(d1 + 16, pm + 8);
        } else {
            float* Ap = Af32 + zofA + (size_t)(m0 + a_row) * lda + kt + a_seg;
            float4 raf[4];
#pragma unroll
            for (int q = 0; q < 4; q++) {
                raf[q] = *(const float4*)(Ap + 4 * q);
                raf[q].x *= anorm; raf[q].y *= anorm;
                raf[q].z *= anorm; raf[q].w *= anorm;
                *(float4*)(Ap + 4 * q) = raf[q];   // write back normalized P (attn output)
            }
#pragma unroll
            for (int q = 0; q < 4; q++) {
                uint32_t hi, mid;
                cvt_pair(raf[q].x, raf[q].y, hi, mid);
                *(uint32_t*)&ASM(bb, 0, a_row, a_seg + 4 * q)     = hi;
                *(uint32_t*)&ASM(bb, 1, a_row, a_seg + 4 * q)     = mid;
                cvt_pair(raf[q].z, raf[q].w, hi, mid);
                *(uint32_t*)&ASM(bb, 0, a_row, a_seg + 4 * q + 2) = hi;
                *(uint32_t*)&ASM(bb, 1, a_row, a_seg + 4 * q + 2) = mid;
            }
        }
        if (BTRANS == 0) {
            const __nv_bfloat16* ph = Bhi + zofB + (size_t)(n0 + a_row) * ldb + kt + a_seg;
            const __nv_bfloat16* pm = Bmid + zofB + (size_t)(n0 + a_row) * ldb + kt + a_seg;
            uint32_t d0 = bsm_u32 + (uint32_t)((((bb * 2 + 0) * BN + a_row) * BKP + a_seg) * 2);
            uint32_t d1 = bsm_u32 + (uint32_t)((((bb * 2 + 1) * BN + a_row) * BKP + a_seg) * 2);
            cp_async16(d0,      ph);
            cp_async16(d0 + 16, ph + 8);
            cp_async16(d1,      pm);
            cp_async16(d1 + 16, pm + 8);
        } else {
            const __nv_bfloat16* ph = Bhi + zofB + (size_t)(kt + bt_k) * ldb + n0 + bt_sg;
            const __nv_bfloat16* pm = Bmid + zofB + (size_t)(kt + bt_k) * ldb + n0 + bt_sg;
            uint32_t d0 = bsm_u32 + (uint32_t)((((bb * 2 + 0) * BK + bt_k) * BNP + bt_sg) * 2);
            uint32_t d1 = bsm_u32 + (uint32_t)((((bb * 2 + 1) * BK + bt_k) * BNP + bt_sg) * 2);
            cp_async16(d0, ph);
            cp_async16(d1, pm);
        }
    };

    const int iters = K / BK;

    issue_tile(0, 0);
    CP_COMMIT();
    CP_WAIT0();
    __syncthreads();

    for (int it = 0; it < iters; it++) {
        const int buf = it & 1;
        const bool more = (it + 1 < iters);
        if (more) {
            issue_tile((it + 1) * BK, buf ^ 1);   // overlaps with compute below
            CP_COMMIT();
        }

#pragma unroll
        for (int ks = 0; ks < BK; ks += 16) {
            uint32_t af[2][MF][4], bf[2][NF][2];
#pragma unroll
            for (int s = 0; s < 2; s++) {
#pragma unroll
                for (int i = 0; i < MF; i++) {
                    int row = wm * WM + i * 16 + a_row_off;
                    int col = ks + a_col_off;
                    uint32_t addr = asm_u32 +
                        (uint32_t)((((buf * 2 + s) * BM + row) * BKP + col) * 2);
                    ldsm_x4(af[s][i], addr);
                }
#pragma unroll
                for (int jj = 0; jj < NF / 2; jj++) {
                    uint32_t r[4];
                    if (BTRANS == 0) {
                        int row = wn * WN + jj * 16 + b_row_off;
                        int col = ks + b_col_off;
                        uint32_t addr = bsm_u32 +
                            (uint32_t)((((buf * 2 + s) * BN + row) * BKP + col) * 2);
                        ldsm_x4(r, addr);
                    } else {
                        int kR = ks + bt_k_off;
                        int nB = wn * WN + jj * 16 + bt_n_off;
                        uint32_t addr = bsm_u32 +
                            (uint32_t)((((buf * 2 + s) * BK + kR) * BNP + nB) * 2);
                        ldsm_x4_t(r, addr);
                    }
                    bf[s][jj * 2 + 0][0] = r[0]; bf[s][jj * 2 + 0][1] = r[1];
                    bf[s][jj * 2 + 1][0] = r[2]; bf[s][jj * 2 + 1][1] = r[3];
                }
            }
#pragma unroll
            for (int i = 0; i < MF; i++)
#pragma unroll
                for (int j = 0; j < NF; j++) {
                    mma16816(acc[i][j], af[0][i], bf[0][j]);   // hi*hi
                    mma16816(acc[i][j], af[0][i], bf[1][j]);   // hi*mid
                    mma16816(acc[i][j], af[1][i], bf[0][j]);   // mid*hi
                }
        }

        if (more) CP_WAIT0();
        __syncthreads();
    }

    // ---- epilogue ----
    if (OUT == 1) {
        float* C = Cf + zofC;
        float rs[MF][2];
#pragma unroll
        for (int i = 0; i < MF; i++) { rs[i][0] = 0.0f; rs[i][1] = 0.0f; }
#pragma unroll
        for (int i = 0; i < MF; i++) {
            int r = m0 + wm * WM + i * 16 + g;
#pragma unroll
            for (int j = 0; j < NF; j++) {
                int c = n0 + wn * WN + j * 8 + t2;
                float e0 = __expf(alpha * acc[i][j][0]);
                float e1 = __expf(alpha * acc[i][j][1]);
                float e2 = __expf(alpha * acc[i][j][2]);
                float e3 = __expf(alpha * acc[i][j][3]);
                *(float2*)&C[(size_t)r * ldc + c]       = make_float2(e0, e1);
                *(float2*)&C[(size_t)(r + 8) * ldc + c] = make_float2(e2, e3);
                rs[i][0] += e0 + e1;
                rs[i][1] += e2 + e3;
            }
        }
#pragma unroll
        for (int i = 0; i < MF; i++) {
            rs[i][0] += __shfl_xor_sync(0xffffffffu, rs[i][0], 1);
            rs[i][0] += __shfl_xor_sync(0xffffffffu, rs[i][0], 2);
            rs[i][1] += __shfl_xor_sync(0xffffffffu, rs[i][1], 1);
            rs[i][1] += __shfl_xor_sync(0xffffffffu, rs[i][1], 2);
        }
        if ((lane & 3) == 0) {
            size_t base = (size_t)z * SEQ + m0 + wm * WM;
#pragma unroll
            for (int i = 0; i < MF; i++) {
                atomicAdd(&rowsum[base + i * 16 + g],     rs[i][0]);
                atomicAdd(&rowsum[base + i * 16 + 8 + g], rs[i][1]);
            }
        }
    } else if (OUT == 2) {
        __nv_bfloat16* Ch = Chi + zofC;
        __nv_bfloat16* Cm = Cmid + zofC;
#pragma unroll
        for (int i = 0; i < MF; i++) {
            int r = m0 + wm * WM + i * 16 + g;
#pragma unroll
            for (int j = 0; j < NF; j++) {
                int c = n0 + wn * WN + j * 8 + t2;
                uint32_t h, mm;
                cvt_pair(acc[i][j][0], acc[i][j][1], h, mm);
                *(uint32_t*)&Ch[(size_t)r * ldc + c] = h;
                *(uint32_t*)&Cm[(size_t)r * ldc + c] = mm;
                cvt_pair(acc[i][j][2], acc[i][j][3], h, mm);
                *(uint32_t*)&Ch[(size_t)(r + 8) * ldc + c] = h;
                *(uint32_t*)&Cm[(size_t)(r + 8) * ldc + c] = mm;
            }
        }
    } else {
        float* C = Cf + zofC;
#pragma unroll
        for (int i = 0; i < MF; i++) {
            int r = m0 + wm * WM + i * 16 + g;
#pragma unroll
            for (int j = 0; j < NF; j++) {
                int c = n0 + wn * WN + j * 8 + t2;
                float b0 = bias ? bias[c]     : 0.0f;
                float b1 = bias ? bias[c + 1] : 0.0f;
                *(float2*)&C[(size_t)r * ldc + c] =
                    make_float2(acc[i][j][0] + b0, acc[i][j][1] + b1);
                *(float2*)&C[(size_t)(r + 8) * ldc + c] =
                    make_float2(acc[i][j][2] + b0, acc[i][j][3] + b1);
            }
        }
    }
#undef ASM
#undef BSM
#undef BSMT
}

// ---------------------------------------------------------------------------
extern "C" void kernel_launch(void* const* d_in, const int* in_sizes, int n_in,
                              void* d_out, int out_size)
{
    const float* x      = (const float*)d_in[0];   // [8,1024,768]
    const float* qkv_w  = (const float*)d_in[1];   // [2304,768]
    const float* proj_w = (const float*)d_in[2];   // [768,768]
    const float* proj_b = (const float*)d_in[3];   // [768]

    float* out_proj = (float*)d_out;                          // [8,1024,768]
    float* out_attn = (float*)d_out + (size_t)MTOK * CDIM;    // [8,12,1024,1024]

    __nv_bfloat16 *x_hi, *x_mid, *wq_hi, *wq_mid, *wp_hi, *wp_mid;
    __nv_bfloat16 *qkv_hi, *qkv_mid, *ctx_hi, *ctx_mid;
    float* rsum;
    cudaGetSymbolAddress((void**)&x_hi,   g_x_hi);
    cudaGetSymbolAddress((void**)&x_mid,  g_x_mid);
    cudaGetSymbolAddress((void**)&wq_hi,  g_wqkv_hi);
    cudaGetSymbolAddress((void**)&wq_mid, g_wqkv_mid);
    cudaGetSymbolAddress((void**)&wp_hi,  g_wproj_hi);
    cudaGetSymbolAddress((void**)&wp_mid, g_wproj_mid);
    cudaGetSymbolAddress((void**)&qkv_hi, g_qkv_hi);
    cudaGetSymbolAddress((void**)&qkv_mid,g_qkv_mid);
    cudaGetSymbolAddress((void**)&ctx_hi, g_ctx_hi);
    cudaGetSymbolAddress((void**)&ctx_mid,g_ctx_mid);
    cudaGetSymbolAddress((void**)&rsum,   g_rowsum);

    constexpr int BKP = 40, BNP = 72;
    constexpr int SM_KC = (4 * 128 * BKP + 4 * 128 * BKP) * 2;   // 81920 B
    constexpr int SM_TR = (4 * 128 * BKP + 4 * 32 * BNP) * 2;    // 59392 B

    cudaFuncSetAttribute((const void*)gemm3<128,128,64,32,0,0,2>,
                         cudaFuncAttributeMaxDynamicSharedMemorySize, SM_KC);
    cudaFuncSetAttribute((const void*)gemm3<128,128,64,32,0,0,1>,
                         cudaFuncAttributeMaxDynamicSharedMemorySize, SM_KC);
    cudaFuncSetAttribute((const void*)gemm3<128,64,32,32,1,1,2>,
                         cudaFuncAttributeMaxDynamicSharedMemorySize, SM_TR);
    cudaFuncSetAttribute((const void*)gemm3<128,128,64,32,0,0,0>,
                         cudaFuncAttributeMaxDynamicSharedMemorySize, SM_KC);

    // 0) fused prep: splits + rowsum zero (one launch)
    {
        int total = N4_X + N4_WQ + N4_WP + N4_RS;
        prep_kernel<<<(total + 255) / 256, 256>>>(
            x, qkv_w, proj_w, x_hi, x_mid, wq_hi, wq_mid, wp_hi, wp_mid, rsum);
    }

    // 1) QKV GEMM -> split planes g_qkv
    gemm3<128,128,64,32,0,0,2><<<dim3(QKVC/128, MTOK/128, 1), 256, SM_KC>>>(
        x_hi, x_mid, nullptr, CDIM, 0, 0,
        wq_hi, wq_mid, CDIM, 0, 0,
        nullptr, qkv_hi, qkv_mid, QKVC, 0, 0,
        CDIM, 1, 1.0f, nullptr, rsum);

    // 2) E = exp(0.125 * Q @ K^T) -> out_attn (fp32), rowsums
    gemm3<128,128,64,32,0,0,1><<<dim3(SEQ/128, SEQ/128, BATCH*HEADS), 256, SM_KC>>>(
        qkv_hi, qkv_mid, nullptr, QKVC, (long long)SEQ * QKVC, 64,
        qkv_hi + CDIM, qkv_mid + CDIM, QKVC, (long long)SEQ * QKVC, 64,
        out_attn, nullptr, nullptr, SEQ,
        (long long)HEADS * SEQ * SEQ, (long long)SEQ * SEQ,
        64, HEADS, 0.125f, nullptr, rsum);

    // 3) ctx = P @ V; normalizes E->P in place (attn output), V via ldmatrix.trans
    gemm3<128,64,32,32,1,1,2><<<dim3(1, SEQ/128, BATCH*HEADS), 256, SM_TR>>>(
        nullptr, nullptr, out_attn, SEQ,
        (long long)HEADS * SEQ * SEQ, (long long)SEQ * SEQ,
        qkv_hi + 2 * CDIM, qkv_mid + 2 * CDIM, QKVC, (long long)SEQ * QKVC, 64,
        nullptr, ctx_hi, ctx_mid, CDIM, (long long)SEQ * CDIM, 64,
        SEQ, HEADS, 1.0f, nullptr, rsum);

    // 4) proj: ctx @ proj_w^T + bias -> out (fp32)
    gemm3<128,128,64,32,0,0,0><<<dim3(CDIM/128, MTOK/128, 1), 256, SM_KC>>>(
        ctx_hi, ctx_mid, nullptr, CDIM, 0, 0,
        wp_hi, wp_mid, CDIM, 0, 0,
        out_proj, nullptr, nullptr, CDIM, 0, 0,
        CDIM, 1, 1.0f, proj_b, rsum);
}